// round 14
// baseline (speedup 1.0000x reference)
#include <cuda_runtime.h>
#include <math.h>

// Problem constants (fixed by this dataset instance)
constexpr int B = 16, P = 19248, C = 81, G = 16;
constexpr float VAR0 = 0.1f, VAR1 = 0.2f;
constexpr float POS_T = 0.5f, NEG_T = 0.4f;
constexpr int   NPR = 3;
constexpr float BBOX_ALPHA = 1.5f, CONF_ALPHA = 1.0f;

constexpr int TILE = 48;            // priors per k_conf block (48*401 == P exactly)
constexpr int CONF_THREADS = 384;   // 8 threads per prior row
constexpr int NB1 = 2048;           // bits >> 20   (bit31 == 0 since lc >= 0 clamped)
constexpr int SCAND_CAP = 5120;     // smem candidate slots (40KB)

// -------- scratch (device globals; no allocation allowed) --------
__device__ unsigned long long g_bestgt[B * G];
__device__ float              g_sl1   [B * P];
__device__ unsigned           g_lcbits[B * P];
__device__ float              g_ce    [B * P];
__device__ unsigned char      g_state [B * P];   // 0=neg, 1=pos, 2=neutral
__device__ int                g_numpos[B];
__device__ unsigned           g_h1    [B * NB1];
__device__ unsigned long long g_cand  [B * P];   // gather overflow only
__device__ double             g_acc   [2];
__device__ unsigned           g_done;

// -------- kernel 0: reset (zero 128KB hist + scalars) --------
__global__ void k_reset() {
    int id = blockIdx.x * 1024 + threadIdx.x;
    if (id < B * NB1) g_h1[id] = 0u;
    if (blockIdx.x == 0) {
        int t = threadIdx.x;
        if (t < B * G) g_bestgt[t] = 0ULL;
        if (t < B)     g_numpos[t] = 0;
        if (t < 2)     g_acc[t] = 0.0;
        if (t == 0)    g_done = 0u;
    }
}

// -------- kernel 1: per-GT best prior only --------
__global__ void k_match(const float4* __restrict__ priors4,
                        const float* __restrict__ gtb) {
    __shared__ float sg[G * 4];
    __shared__ float sga[G];
    __shared__ unsigned long long sbest[G];
    int b = blockIdx.y;
    int t = threadIdx.x;
    if (t < G * 4) sg[t] = gtb[b * G * 4 + t];
    if (t < G)     sbest[t] = 0ULL;
    __syncthreads();
    if (t < G)     sga[t] = (sg[t*4+2] - sg[t*4+0]) * (sg[t*4+3] - sg[t*4+1]);
    __syncthreads();

    int p = blockIdx.x * blockDim.x + t;
    if (p < P) {
        float4 pr = priors4[(size_t)b * P + p];
        float bx1 = pr.x - 0.5f * pr.z, by1 = pr.y - 0.5f * pr.w;
        float bx2 = pr.x + 0.5f * pr.z, by2 = pr.y + 0.5f * pr.w;
        float areaB = pr.z * pr.w;
        #pragma unroll
        for (int g = 0; g < G; g++) {
            float iw = fmaxf(fminf(sg[g*4+2], bx2) - fmaxf(sg[g*4+0], bx1), 0.0f);
            float ih = fmaxf(fminf(sg[g*4+3], by2) - fmaxf(sg[g*4+1], by1), 0.0f);
            float inter = iw * ih;
            float iou = inter / fmaxf(sga[g] + areaB - inter, 1e-10f);
            unsigned long long key =
                ((unsigned long long)__float_as_uint(iou) << 32) |
                (unsigned long long)(0xFFFFFFFFu - (unsigned)p);  // max iou, then min p
            atomicMax(&sbest[g], key);
        }
    }
    __syncthreads();
    if (t < G) atomicMax(&g_bestgt[b * G + t], sbest[t]);
}

// -------- kernel 2: conf loss + match recompute + force-match + SL1 + level-1 hist --------
__global__ __launch_bounds__(CONF_THREADS)
void k_conf(const float* __restrict__ conf,
            const float* __restrict__ loc,
            const float* __restrict__ priors,
            const float* __restrict__ gtb,
            const int*   __restrict__ gtl) {
    __shared__ float sconf[TILE * C];          // 15552 B
    __shared__ int   sbestp[G];
    __shared__ int   slab[G];
    __shared__ float sgb[G * 4];
    __shared__ float sga[G];
    __shared__ int   s_pos[CONF_THREADS / 32];

    int b    = blockIdx.y;
    int tile = blockIdx.x;
    int t    = threadIdx.x;

    if (t < G) {
        unsigned long long key = g_bestgt[b * G + t];
        sbestp[t] = (int)(0xFFFFFFFFu - (unsigned)(key & 0xFFFFFFFFull));
        slab[t]   = gtl[b * G + t];
    }
    if (t < G * 4) sgb[t] = gtb[b * G * 4 + t];

    {
        const float4* src = (const float4*)(conf + ((size_t)b * P + (size_t)tile * TILE) * C);
        float4* dst = (float4*)sconf;
        constexpr int N4 = TILE * C / 4;   // 972
        for (int i = t; i < N4; i += CONF_THREADS) dst[i] = src[i];
    }
    __syncthreads();
    if (t < G) sga[t] = (sgb[t*4+2] - sgb[t*4+0]) * (sgb[t*4+3] - sgb[t*4+1]);
    __syncthreads();

    int row = t >> 3;           // 0..47
    int sub = t & 7;            // 0..7
    const float* srow = sconf + row * C;

    float v[11];
    #pragma unroll
    for (int i = 0; i < 11; i++) {
        int j = sub + i * 8;
        v[i] = (j < C) ? srow[j] : -1e30f;
    }
    float m = v[0];
    #pragma unroll
    for (int i = 1; i < 11; i++) m = fmaxf(m, v[i]);
    m = fmaxf(m, __shfl_xor_sync(0xffffffffu, m, 1));
    m = fmaxf(m, __shfl_xor_sync(0xffffffffu, m, 2));
    m = fmaxf(m, __shfl_xor_sync(0xffffffffu, m, 4));
    float s = 0.0f;
    #pragma unroll
    for (int i = 0; i < 11; i++) s += __expf(v[i] - m);
    s += __shfl_xor_sync(0xffffffffu, s, 1);
    s += __shfl_xor_sync(0xffffffffu, s, 2);
    s += __shfl_xor_sync(0xffffffffu, s, 4);

    bool is_pos = false;
    if (sub == 0) {
        float lse = m + logf(s);
        int p   = tile * TILE + row;
        int idx = b * P + p;
        // recompute per-prior match (bit-identical to k_match arithmetic)
        const float4 pr = *(const float4*)(priors + (size_t)idx * 4);
        float bx1 = pr.x - 0.5f * pr.z, by1 = pr.y - 0.5f * pr.w;
        float bx2 = pr.x + 0.5f * pr.z, by2 = pr.y + 0.5f * pr.w;
        float areaB = pr.z * pr.w;
        float bo = -1.0f; int bi = 0;
        #pragma unroll
        for (int g = 0; g < G; g++) {
            float iw = fmaxf(fminf(sgb[g*4+2], bx2) - fmaxf(sgb[g*4+0], bx1), 0.0f);
            float ih = fmaxf(fminf(sgb[g*4+3], by2) - fmaxf(sgb[g*4+1], by1), 0.0f);
            float inter = iw * ih;
            float iou = inter / fmaxf(sga[g] + areaB - inter, 1e-10f);
            if (iou > bo) { bo = iou; bi = g; }   // first-index argmax
        }
        // force-match (ascending g == sequential scatter, last wins)
        #pragma unroll
        for (int g = 0; g < G; g++)
            if (sbestp[g] == p) { bo = 2.0f; bi = g; }

        int lab = slab[bi];
        int conf_t = (bo < POS_T) ? ((bo < NEG_T) ? 0 : -1) : lab;
        bool pos = conf_t > 0;
        is_pos = pos;
        int tgt = pos ? conf_t : 0;
        float ce = lse - srow[tgt];
        float lc = (pos || conf_t < 0) ? 0.0f : fmaxf(lse - srow[0], 0.0f);
        unsigned bits = __float_as_uint(lc);      // lc >= 0: bits monotonic, bin < 2048
        g_ce[idx]     = ce;
        g_lcbits[idx] = bits;
        g_state[idx]  = pos ? 1 : (conf_t < 0 ? 2 : 0);

        // warp-aggregated level-1 histogram update
        unsigned bin = bits >> 20;
        unsigned amask = __activemask();
        unsigned same = __match_any_sync(amask, bin);
        int lane = t & 31;
        int leader = __ffs(same) - 1;
        if (lane == leader) atomicAdd(&g_h1[b * NB1 + bin], (unsigned)__popc(same));

        float sl = 0.0f;
        if (pos) {
            const float4 ld = *(const float4*)(loc + (size_t)idx * 4);
            float gx1 = sgb[bi*4+0], gy1 = sgb[bi*4+1];
            float gx2 = sgb[bi*4+2], gy2 = sgb[bi*4+3];
            float t0 = ((gx1 + gx2) * 0.5f - pr.x) / (VAR0 * pr.z);
            float t1 = ((gy1 + gy2) * 0.5f - pr.y) / (VAR0 * pr.w);
            float t2 = logf(fmaxf((gx2 - gx1) / pr.z, 1e-8f)) / VAR1;
            float t3 = logf(fmaxf((gy2 - gy1) / pr.w, 1e-8f)) / VAR1;
            float d;
            d = ld.x - t0; sl += (fabsf(d) < 1.0f) ? 0.5f * d * d : fabsf(d) - 0.5f;
            d = ld.y - t1; sl += (fabsf(d) < 1.0f) ? 0.5f * d * d : fabsf(d) - 0.5f;
            d = ld.z - t2; sl += (fabsf(d) < 1.0f) ? 0.5f * d * d : fabsf(d) - 0.5f;
            d = ld.w - t3; sl += (fabsf(d) < 1.0f) ? 0.5f * d * d : fabsf(d) - 0.5f;
        }
        g_sl1[idx] = sl;
    }
    unsigned bal = __ballot_sync(0xffffffffu, is_pos);
    if ((t & 31) == 0) s_pos[t >> 5] = __popc(bal);
    __syncthreads();
    if (t == 0) {
        int c = 0;
        #pragma unroll
        for (int w = 0; w < CONF_THREADS / 32; w++) c += s_pos[w];
        if (c) atomicAdd(&g_numpos[b], c);
    }
}

// ---- shuffle-based block suffix sum (1024 threads): returns sum_{j>=t} c_j ----
__device__ __forceinline__ int block_suffix_incl(int c, int t, int* wsmem) {
    int lane = t & 31, w = t >> 5;
    int v = c;
    #pragma unroll
    for (int off = 1; off < 32; off <<= 1) {
        int u = __shfl_down_sync(0xffffffffu, v, off);
        if (lane + off < 32) v += u;
    }
    if (lane == 0) wsmem[w] = v;   // warp total
    __syncthreads();
    if (t < 32) {
        int x = wsmem[t];
        #pragma unroll
        for (int off = 1; off < 32; off <<= 1) {
            int u = __shfl_down_sync(0xffffffffu, x, off);
            if (t + off < 32) x += u;
        }
        wsmem[t] = x;              // suffix of warp totals, incl own warp
    }
    __syncthreads();
    int add = (w + 1 < 32) ? wsmem[w + 1] : 0;
    return v + add;
}

// -------- kernel 3: sel1 + gather + in-smem radix pick + final sums + out --------
__global__ __launch_bounds__(1024)
void k_selpick(float* __restrict__ out) {
    __shared__ unsigned long long scand[SCAND_CAP];   // 40KB
    __shared__ unsigned hist[1024];
    __shared__ int wsmem[32];
    __shared__ int s_bin, s_r, s_n;
    __shared__ float sB[32], sC[32];

    int b = blockIdx.x, t = threadIdx.x;
    const unsigned* lc = g_lcbits + b * P;
    int numpos = g_numpos[b];
    int k = NPR * numpos;
    if (k > P - 1) k = P - 1;

    // ---- level-1 boundary from histogram only (2 bins/thread, desc order) ----
    {
        const unsigned* h = g_h1 + b * NB1;
        int c0 = (int)h[2 * t], c1 = (int)h[2 * t + 1];
        int S = block_suffix_incl(c0 + c1, t, wsmem);
        int above = S - c0 - c1;
        if (above < k && k <= above + c1) { s_bin = 2 * t + 1; s_r = k - above; }
        else if (above + c1 < k && k <= above + c1 + c0) { s_bin = 2 * t; s_r = k - above - c1; }
        if (t == 0) s_n = 0;
    }
    __syncthreads();
    int hb1 = s_bin;
    int r   = s_r;

    // ---- gather boundary-bin candidates (unique keys; order irrelevant) ----
    for (int p = t; p < P; p += 1024) {
        unsigned bits = lc[p];
        if ((int)(bits >> 20) == hb1) {
            int slot = atomicAdd(&s_n, 1);
            unsigned long long key =
                ((unsigned long long)bits << 32) |
                (unsigned long long)(0xFFFFFFFFu - (unsigned)p);
            if (slot < SCAND_CAP) scand[slot] = key;
            else g_cand[(size_t)b * P + (slot - SCAND_CAP)] = key;
        }
    }
    __syncthreads();
    int n = s_n;

    // ---- 4-level radix select of r-th largest key among n candidates ----
    // key bits: [63:52]=lc[31:20] (const hb1), [51:42]=lc[19:10], [41:32]=lc[9:0],
    //           [31:15]=const 1s (~p, p<32768), [14:0]=low bits of ~p
    unsigned long long pmask = 0ULL, pval = 0ULL;
    const int LS[4] = {42, 32, 5, 0};
    const int LW[4] = {10, 10, 10, 5};
    #pragma unroll
    for (int L = 0; L < 4; L++) {
        int sft = LS[L], nb = 1 << LW[L];
        hist[t] = 0u;
        __syncthreads();
        for (int i = t; i < n; i += 1024) {
            unsigned long long key = (i < SCAND_CAP) ? scand[i]
                                   : g_cand[(size_t)b * P + (i - SCAND_CAP)];
            if ((key & pmask) == pval)
                atomicAdd(&hist[(unsigned)((key >> sft) & (unsigned long long)(nb - 1))], 1u);
        }
        __syncthreads();
        int c = (t < nb) ? (int)hist[t] : 0;
        int S = block_suffix_incl(c, t, wsmem);
        int above = S - c;
        if (t < nb && above < r && r <= above + c) { s_bin = t; s_r = r - above; }
        __syncthreads();
        pval  |= ((unsigned long long)s_bin) << sft;
        pmask |= ((unsigned long long)(nb - 1)) << sft;
        r = s_r;
        __syncthreads();
    }
    unsigned long long selkey = ((unsigned long long)(unsigned)hb1 << 52)
                              | pval
                              | (0x1FFFFull << 15);
    unsigned T = (unsigned)(selkey >> 32);
    int cut = (int)(0xFFFFFFFFu - (unsigned)(selkey & 0xFFFFFFFFull));

    // ---- final masked sums for this image ----
    float invnp = 1.0f / (float)max(numpos, 1);
    float cB = 0.0f, cC = 0.0f;
    for (int p = t; p < P; p += 1024) {
        int idx = b * P + p;
        int st = g_state[idx];
        unsigned bits = lc[p];
        bool neg = (st == 0) && (bits > T || (bits == T && p <= cut));
        bool pos = (st == 1);
        if (pos) cB += g_sl1[idx] * invnp;
        if (pos || neg) cC += g_ce[idx];
    }
    #pragma unroll
    for (int o = 16; o > 0; o >>= 1) {
        cB += __shfl_xor_sync(0xffffffffu, cB, o);
        cC += __shfl_xor_sync(0xffffffffu, cC, o);
    }
    int w = t >> 5;
    if ((t & 31) == 0) { sB[w] = cB; sC[w] = cC; }
    __syncthreads();
    if (t == 0) {
        float tB = 0.0f, tC = 0.0f;
        #pragma unroll
        for (int i = 0; i < 32; i++) { tB += sB[i]; tC += sC[i]; }
        atomicAdd(&g_acc[0], (double)tB);
        atomicAdd(&g_acc[1], (double)tC);
        __threadfence();
        unsigned old = atomicAdd(&g_done, 1u);
        if (old == B - 1) {
            out[0] = (float)(g_acc[0] * (double)BBOX_ALPHA / (double)B);
            out[1] = (float)(g_acc[1] * (double)CONF_ALPHA / (double)B);
        }
    }
}

extern "C" void kernel_launch(void* const* d_in, const int* in_sizes, int n_in,
                              void* d_out, int out_size) {
    const float* loc    = (const float*)d_in[0];
    const float* conf   = (const float*)d_in[1];
    const float* priors = (const float*)d_in[2];
    const float* gtb    = (const float*)d_in[3];
    const int*   gtl    = (const int*)d_in[4];
    float* out = (float*)d_out;

    k_reset<<<(B * NB1 + 1023) / 1024, 1024>>>();
    {
        dim3 grid((P + 255) / 256, B);
        k_match<<<grid, 256>>>((const float4*)priors, gtb);
    }
    {
        dim3 grid(P / TILE, B);   // 401 x 16
        k_conf<<<grid, CONF_THREADS>>>(conf, loc, priors, gtb, gtl);
    }
    k_selpick<<<B, 1024>>>(out);
}

// round 15
// speedup vs baseline: 1.5915x; 1.5915x over previous
#include <cuda_runtime.h>
#include <math.h>

// Problem constants (fixed by this dataset instance)
constexpr int B = 16, P = 19248, C = 81, G = 16;
constexpr float VAR0 = 0.1f, VAR1 = 0.2f;
constexpr float POS_T = 0.5f, NEG_T = 0.4f;
constexpr int   NPR = 3;
constexpr float BBOX_ALPHA = 1.5f, CONF_ALPHA = 1.0f;

constexpr int TILE = 48;            // priors per k_conf block (48*401 == P exactly)
constexpr int CONF_THREADS = 384;   // 8 threads per prior row

// -------- scratch (device globals; no allocation allowed) --------
__device__ unsigned long long g_bestgt[B * G];
__device__ float              g_btover[B * P];
__device__ int                g_btidx [B * P];
__device__ unsigned           g_lcbits[B * P];
__device__ int                g_numpos[B];
__device__ double             g_sumB  [B];      // raw smooth-L1 sum over positives
__device__ double             g_sumC  [B];      // CE sum over positives
__device__ double             g_acc   [2];
__device__ unsigned           g_done;

// -------- kernel 0: reset (single tiny block) --------
__global__ void k_reset() {
    int t = threadIdx.x;
    if (t < B * G) g_bestgt[t] = 0ULL;
    if (t < B)   { g_numpos[t] = 0; g_sumB[t] = 0.0; g_sumC[t] = 0.0; }
    if (t < 2)     g_acc[t] = 0.0;
    if (t == 0)    g_done = 0u;
}

// -------- kernel 1: per-prior match + per-GT best prior (parallel over P) --------
__global__ void k_match(const float4* __restrict__ priors4,
                        const float* __restrict__ gtb) {
    __shared__ float sg[G * 4];
    __shared__ float sga[G];
    __shared__ unsigned long long sbest[G];
    int b = blockIdx.y;
    int t = threadIdx.x;
    if (t < G * 4) sg[t] = gtb[b * G * 4 + t];
    if (t < G)     sbest[t] = 0ULL;
    __syncthreads();
    if (t < G)     sga[t] = (sg[t*4+2] - sg[t*4+0]) * (sg[t*4+3] - sg[t*4+1]);
    __syncthreads();

    int p = blockIdx.x * blockDim.x + t;
    if (p < P) {
        float4 pr = priors4[(size_t)b * P + p];
        float bx1 = pr.x - 0.5f * pr.z, by1 = pr.y - 0.5f * pr.w;
        float bx2 = pr.x + 0.5f * pr.z, by2 = pr.y + 0.5f * pr.w;
        float areaB = pr.z * pr.w;
        float bo = -1.0f; int bi = 0;
        #pragma unroll
        for (int g = 0; g < G; g++) {
            float iw = fmaxf(fminf(sg[g*4+2], bx2) - fmaxf(sg[g*4+0], bx1), 0.0f);
            float ih = fmaxf(fminf(sg[g*4+3], by2) - fmaxf(sg[g*4+1], by1), 0.0f);
            float inter = iw * ih;
            float iou = inter / fmaxf(sga[g] + areaB - inter, 1e-10f);
            if (iou > bo) { bo = iou; bi = g; }   // first-index argmax
            unsigned long long key =
                ((unsigned long long)__float_as_uint(iou) << 32) |
                (unsigned long long)(0xFFFFFFFFu - (unsigned)p);  // max iou, then min p
            atomicMax(&sbest[g], key);
        }
        g_btover[b * P + p] = bo;
        g_btidx [b * P + p] = bi;
    }
    __syncthreads();
    if (t < G) atomicMax(&g_bestgt[b * G + t], sbest[t]);
}

// -------- kernel 2: conf lse + targets + SL1; accumulates per-image pos sums --------
__global__ __launch_bounds__(CONF_THREADS)
void k_conf(const float* __restrict__ conf,
            const float* __restrict__ loc,
            const float* __restrict__ priors,
            const float* __restrict__ gtb,
            const int*   __restrict__ gtl) {
    __shared__ float sconf[TILE * C];          // 15552 B
    __shared__ int   sbestp[G];
    __shared__ int   slab[G];
    __shared__ float sgb[G * 4];
    __shared__ int   s_pos[CONF_THREADS / 32];
    __shared__ float s_sB[CONF_THREADS / 32], s_sC[CONF_THREADS / 32];

    int b    = blockIdx.y;
    int tile = blockIdx.x;
    int t    = threadIdx.x;

    if (t < G) {
        unsigned long long key = g_bestgt[b * G + t];
        sbestp[t] = (int)(0xFFFFFFFFu - (unsigned)(key & 0xFFFFFFFFull));
        slab[t]   = gtl[b * G + t];
    }
    if (t < G * 4) sgb[t] = gtb[b * G * 4 + t];

    {
        const float4* src = (const float4*)(conf + ((size_t)b * P + (size_t)tile * TILE) * C);
        float4* dst = (float4*)sconf;
        constexpr int N4 = TILE * C / 4;   // 972
        for (int i = t; i < N4; i += CONF_THREADS) dst[i] = src[i];
    }
    __syncthreads();

    int row = t >> 3;           // 0..47
    int sub = t & 7;            // 0..7
    const float* srow = sconf + row * C;

    float v[11];
    #pragma unroll
    for (int i = 0; i < 11; i++) {
        int j = sub + i * 8;
        v[i] = (j < C) ? srow[j] : -1e30f;
    }
    float m = v[0];
    #pragma unroll
    for (int i = 1; i < 11; i++) m = fmaxf(m, v[i]);
    m = fmaxf(m, __shfl_xor_sync(0xffffffffu, m, 1));
    m = fmaxf(m, __shfl_xor_sync(0xffffffffu, m, 2));
    m = fmaxf(m, __shfl_xor_sync(0xffffffffu, m, 4));
    float s = 0.0f;
    #pragma unroll
    for (int i = 0; i < 11; i++) s += __expf(v[i] - m);
    s += __shfl_xor_sync(0xffffffffu, s, 1);
    s += __shfl_xor_sync(0xffffffffu, s, 2);
    s += __shfl_xor_sync(0xffffffffu, s, 4);

    bool is_pos = false;
    float slv = 0.0f, cev = 0.0f;
    if (sub == 0) {
        float lse = m + logf(s);
        int p   = tile * TILE + row;
        int idx = b * P + p;
        float bo = g_btover[idx];
        int   bi = g_btidx[idx];
        // force-match (ascending g == sequential scatter, last wins)
        #pragma unroll
        for (int g = 0; g < G; g++)
            if (sbestp[g] == p) { bo = 2.0f; bi = g; }

        int lab = slab[bi];
        int conf_t = (bo < POS_T) ? ((bo < NEG_T) ? 0 : -1) : lab;
        bool pos = conf_t > 0;
        is_pos = pos;
        // lc for ranking: zero for pos/neutral, lse-conf0 for negatives (>= 0)
        float lc = (pos || conf_t < 0) ? 0.0f : fmaxf(lse - srow[0], 0.0f);
        g_lcbits[idx] = __float_as_uint(lc);
        if (pos) {
            cev = lse - srow[conf_t];   // positive CE
            const float4 pr = *(const float4*)(priors + (size_t)idx * 4);
            const float4 ld = *(const float4*)(loc    + (size_t)idx * 4);
            float gx1 = sgb[bi*4+0], gy1 = sgb[bi*4+1];
            float gx2 = sgb[bi*4+2], gy2 = sgb[bi*4+3];
            float t0 = ((gx1 + gx2) * 0.5f - pr.x) / (VAR0 * pr.z);
            float t1 = ((gy1 + gy2) * 0.5f - pr.y) / (VAR0 * pr.w);
            float t2 = logf(fmaxf((gx2 - gx1) / pr.z, 1e-8f)) / VAR1;
            float t3 = logf(fmaxf((gy2 - gy1) / pr.w, 1e-8f)) / VAR1;
            float d;
            d = ld.x - t0; slv += (fabsf(d) < 1.0f) ? 0.5f * d * d : fabsf(d) - 0.5f;
            d = ld.y - t1; slv += (fabsf(d) < 1.0f) ? 0.5f * d * d : fabsf(d) - 0.5f;
            d = ld.z - t2; slv += (fabsf(d) < 1.0f) ? 0.5f * d * d : fabsf(d) - 0.5f;
            d = ld.w - t3; slv += (fabsf(d) < 1.0f) ? 0.5f * d * d : fabsf(d) - 0.5f;
        }
    }
    // block-reduce numpos, sumSL1, sumPosCE
    unsigned bal = __ballot_sync(0xffffffffu, is_pos);
    #pragma unroll
    for (int o = 16; o > 0; o >>= 1) {
        slv += __shfl_xor_sync(0xffffffffu, slv, o);
        cev += __shfl_xor_sync(0xffffffffu, cev, o);
    }
    int w = t >> 5;
    if ((t & 31) == 0) { s_pos[w] = __popc(bal); s_sB[w] = slv; s_sC[w] = cev; }
    __syncthreads();
    if (t == 0) {
        int c = 0; float tB = 0.0f, tC = 0.0f;
        #pragma unroll
        for (int i = 0; i < CONF_THREADS / 32; i++) { c += s_pos[i]; tB += s_sB[i]; tC += s_sC[i]; }
        if (c)  atomicAdd(&g_numpos[b], c);
        if (tB != 0.0f) atomicAdd(&g_sumB[b], (double)tB);
        if (tC != 0.0f) atomicAdd(&g_sumC[b], (double)tC);
    }
}

// ---- shuffle-based block suffix sum (1024 threads): returns sum_{j>=t} c_j ----
__device__ __forceinline__ int block_suffix_incl(int c, int t, int* wsmem) {
    int lane = t & 31, w = t >> 5;
    int v = c;
    #pragma unroll
    for (int off = 1; off < 32; off <<= 1) {
        int u = __shfl_down_sync(0xffffffffu, v, off);
        if (lane + off < 32) v += u;
    }
    if (lane == 0) wsmem[w] = v;   // warp total
    __syncthreads();
    if (t < 32) {
        int x = wsmem[t];
        #pragma unroll
        for (int off = 1; off < 32; off <<= 1) {
            int u = __shfl_down_sync(0xffffffffu, x, off);
            if (t + off < 32) x += u;
        }
        wsmem[t] = x;              // suffix of warp totals, incl own warp
    }
    __syncthreads();
    int add = (w + 1 < 32) ? wsmem[w + 1] : 0;
    return v + add;
}

// -------- kernel 3: 3-level threshold refinement + masked sum + output --------
// neg-CE identity: for conf_t==0, ce == lc exactly; ties at T all have value T
// (or T==0 contributing 0), so:
//   negCE = sum_{lc_bits > T} lc  +  (k - cntGT) * float(T)
__global__ __launch_bounds__(1024)
void k_select(float* __restrict__ out) {
    __shared__ unsigned hist[2048];   // 8KB, reused across levels
    __shared__ int wsmem[32];
    __shared__ int s_bin, s_r;
    __shared__ double sS[32];
    __shared__ int sN[32];

    int b = blockIdx.x, t = threadIdx.x;
    int lane = t & 31;
    const unsigned* lc = g_lcbits + b * P;
    int numpos = g_numpos[b];
    int k = NPR * numpos;
    if (k > P - 1) k = P - 1;

    // ---- level 1: 2048 bins on bits>>20 (warp-aggregated smem atomics) ----
    hist[t] = 0u; hist[t + 1024] = 0u;
    __syncthreads();
    for (int p = t; p < P; p += 1024) {
        unsigned bin = lc[p] >> 20;
        unsigned act = __activemask();
        unsigned same = __match_any_sync(act, bin);
        if ((__ffs(same) - 1) == lane) atomicAdd(&hist[bin], (unsigned)__popc(same));
    }
    __syncthreads();
    {
        int c0 = (int)hist[2 * t], c1 = (int)hist[2 * t + 1];
        int S = block_suffix_incl(c0 + c1, t, wsmem);
        int above = S - c0 - c1;
        if (above < k && k <= above + c1) { s_bin = 2 * t + 1; s_r = k - above; }
        else if (above + c1 < k && k <= above + c1 + c0) { s_bin = 2 * t; s_r = k - above - c1; }
    }
    __syncthreads();
    int hb1 = s_bin, r = s_r;

    // ---- level 2: 1024 bins on (bits>>10)&0x3FF, predicated ----
    hist[t] = 0u;
    __syncthreads();
    for (int p = t; p < P; p += 1024) {
        unsigned v = lc[p];
        bool in = ((int)(v >> 20) == hb1);
        unsigned act = __activemask();
        unsigned inm = __ballot_sync(act, in);
        if (in) {
            unsigned bin = (v >> 10) & 0x3FFu;
            unsigned same = __match_any_sync(act & inm, bin) & inm;
            if ((__ffs(same) - 1) == lane) atomicAdd(&hist[bin], (unsigned)__popc(same));
        }
    }
    __syncthreads();
    {
        int c = (int)hist[t];
        int S = block_suffix_incl(c, t, wsmem);
        int above = S - c;
        if (above < r && r <= above + c) { s_bin = t; s_r = r - above; }
    }
    __syncthreads();
    unsigned pref = ((unsigned)hb1 << 10) | (unsigned)s_bin;
    r = s_r;
    __syncthreads();

    // ---- level 3: 1024 bins on bits&0x3FF, predicated on top 22 bits ----
    hist[t] = 0u;
    __syncthreads();
    for (int p = t; p < P; p += 1024) {
        unsigned v = lc[p];
        bool in = ((v >> 10) == pref);
        unsigned act = __activemask();
        unsigned inm = __ballot_sync(act, in);
        if (in) {
            unsigned bin = v & 0x3FFu;
            unsigned same = __match_any_sync(act & inm, bin) & inm;
            if ((__ffs(same) - 1) == lane) atomicAdd(&hist[bin], (unsigned)__popc(same));
        }
    }
    __syncthreads();
    {
        int c = (int)hist[t];
        int S = block_suffix_incl(c, t, wsmem);
        int above = S - c;
        if (above < r && r <= above + c) { s_bin = t; s_r = r - above; }
    }
    __syncthreads();
    unsigned T = (pref << 10) | (unsigned)s_bin;   // exact k-th largest lc bits

    // ---- masked sum: S_GT = sum of lc where bits > T; cntGT = count ----
    double S = 0.0; int cnt = 0;
    for (int p = t; p < P; p += 1024) {
        unsigned bits = lc[p];
        if (bits > T) { S += (double)__uint_as_float(bits); cnt++; }
    }
    #pragma unroll
    for (int o = 16; o > 0; o >>= 1) {
        S   += __shfl_xor_sync(0xffffffffu, S, o);
        cnt += __shfl_xor_sync(0xffffffffu, cnt, o);
    }
    int w = t >> 5;
    if (lane == 0) { sS[w] = S; sN[w] = cnt; }
    __syncthreads();
    if (t == 0) {
        double tS = 0.0; int tN = 0;
        #pragma unroll
        for (int i = 0; i < 32; i++) { tS += sS[i]; tN += sN[i]; }
        double negCE = tS + (double)(k - tN) * (double)__uint_as_float(T);
        double lossC = g_sumC[b] + negCE;
        double lossB = g_sumB[b] / (double)max(numpos, 1);
        atomicAdd(&g_acc[0], lossB);
        atomicAdd(&g_acc[1], lossC);
        __threadfence();
        unsigned old = atomicAdd(&g_done, 1u);
        if (old == B - 1) {
            out[0] = (float)(g_acc[0] * (double)BBOX_ALPHA / (double)B);
            out[1] = (float)(g_acc[1] * (double)CONF_ALPHA / (double)B);
        }
    }
}

extern "C" void kernel_launch(void* const* d_in, const int* in_sizes, int n_in,
                              void* d_out, int out_size) {
    const float* loc    = (const float*)d_in[0];
    const float* conf   = (const float*)d_in[1];
    const float* priors = (const float*)d_in[2];
    const float* gtb    = (const float*)d_in[3];
    const int*   gtl    = (const int*)d_in[4];
    float* out = (float*)d_out;

    k_reset<<<1, 256>>>();
    {
        dim3 grid((P + 255) / 256, B);
        k_match<<<grid, 256>>>((const float4*)priors, gtb);
    }
    {
        dim3 grid(P / TILE, B);   // 401 x 16
        k_conf<<<grid, CONF_THREADS>>>(conf, loc, priors, gtb, gtl);
    }
    k_select<<<B, 1024>>>(out);
}

// round 16
// speedup vs baseline: 1.6910x; 1.0625x over previous
#include <cuda_runtime.h>
#include <math.h>

// Problem constants (fixed by this dataset instance)
constexpr int B = 16, P = 19248, C = 81, G = 16;
constexpr float VAR0 = 0.1f, VAR1 = 0.2f;
constexpr float POS_T = 0.5f, NEG_T = 0.4f;
constexpr int   NPR = 3;
constexpr float BBOX_ALPHA = 1.5f, CONF_ALPHA = 1.0f;

constexpr int TILE = 48;            // priors per k_conf block (48*401 == P exactly)
constexpr int CONF_THREADS = 384;   // 8 threads per prior row

// -------- scratch (device globals; no allocation allowed) --------
__device__ unsigned long long g_bestgt[B * G];
__device__ float              g_btover[B * P];
__device__ int                g_btidx [B * P];
__device__ unsigned           g_lcbits[B * P];
__device__ int                g_numpos[B];
__device__ double             g_sumB  [B];      // raw smooth-L1 sum over positives
__device__ double              g_sumC  [B];     // CE sum over positives
__device__ double             g_acc   [2];
__device__ unsigned           g_done;

// -------- kernel 0: reset (single tiny block) --------
__global__ void k_reset() {
    int t = threadIdx.x;
    if (t < B * G) g_bestgt[t] = 0ULL;
    if (t < B)   { g_numpos[t] = 0; g_sumB[t] = 0.0; g_sumC[t] = 0.0; }
    if (t < 2)     g_acc[t] = 0.0;
    if (t == 0)    g_done = 0u;
}

// -------- kernel 1: per-prior match + per-GT best prior (parallel over P) --------
__global__ void k_match(const float4* __restrict__ priors4,
                        const float* __restrict__ gtb) {
    __shared__ float sg[G * 4];
    __shared__ float sga[G];
    __shared__ unsigned long long sbest[G];
    int b = blockIdx.y;
    int t = threadIdx.x;
    if (t < G * 4) sg[t] = gtb[b * G * 4 + t];
    if (t < G)     sbest[t] = 0ULL;
    __syncthreads();
    if (t < G)     sga[t] = (sg[t*4+2] - sg[t*4+0]) * (sg[t*4+3] - sg[t*4+1]);
    __syncthreads();

    int p = blockIdx.x * blockDim.x + t;
    if (p < P) {
        float4 pr = priors4[(size_t)b * P + p];
        float bx1 = pr.x - 0.5f * pr.z, by1 = pr.y - 0.5f * pr.w;
        float bx2 = pr.x + 0.5f * pr.z, by2 = pr.y + 0.5f * pr.w;
        float areaB = pr.z * pr.w;
        float bo = -1.0f; int bi = 0;
        #pragma unroll
        for (int g = 0; g < G; g++) {
            float iw = fmaxf(fminf(sg[g*4+2], bx2) - fmaxf(sg[g*4+0], bx1), 0.0f);
            float ih = fmaxf(fminf(sg[g*4+3], by2) - fmaxf(sg[g*4+1], by1), 0.0f);
            float inter = iw * ih;
            float iou = inter / fmaxf(sga[g] + areaB - inter, 1e-10f);
            if (iou > bo) { bo = iou; bi = g; }   // first-index argmax
            unsigned long long key =
                ((unsigned long long)__float_as_uint(iou) << 32) |
                (unsigned long long)(0xFFFFFFFFu - (unsigned)p);  // max iou, then min p
            atomicMax(&sbest[g], key);
        }
        g_btover[b * P + p] = bo;
        g_btidx [b * P + p] = bi;
    }
    __syncthreads();
    if (t < G) atomicMax(&g_bestgt[b * G + t], sbest[t]);
}

// -------- kernel 2: conf lse + targets + SL1; accumulates per-image pos sums --------
__global__ __launch_bounds__(CONF_THREADS)
void k_conf(const float* __restrict__ conf,
            const float* __restrict__ loc,
            const float* __restrict__ priors,
            const float* __restrict__ gtb,
            const int*   __restrict__ gtl) {
    __shared__ float sconf[TILE * C];          // 15552 B
    __shared__ int   sbestp[G];
    __shared__ int   slab[G];
    __shared__ float sgb[G * 4];
    __shared__ int   s_pos[CONF_THREADS / 32];
    __shared__ float s_sB[CONF_THREADS / 32], s_sC[CONF_THREADS / 32];

    int b    = blockIdx.y;
    int tile = blockIdx.x;
    int t    = threadIdx.x;

    if (t < G) {
        unsigned long long key = g_bestgt[b * G + t];
        sbestp[t] = (int)(0xFFFFFFFFu - (unsigned)(key & 0xFFFFFFFFull));
        slab[t]   = gtl[b * G + t];
    }
    if (t < G * 4) sgb[t] = gtb[b * G * 4 + t];

    {
        const float4* src = (const float4*)(conf + ((size_t)b * P + (size_t)tile * TILE) * C);
        float4* dst = (float4*)sconf;
        constexpr int N4 = TILE * C / 4;   // 972
        for (int i = t; i < N4; i += CONF_THREADS) dst[i] = src[i];
    }
    __syncthreads();

    int row = t >> 3;           // 0..47
    int sub = t & 7;            // 0..7
    const float* srow = sconf + row * C;

    float v[11];
    #pragma unroll
    for (int i = 0; i < 11; i++) {
        int j = sub + i * 8;
        v[i] = (j < C) ? srow[j] : -1e30f;
    }
    float m = v[0];
    #pragma unroll
    for (int i = 1; i < 11; i++) m = fmaxf(m, v[i]);
    m = fmaxf(m, __shfl_xor_sync(0xffffffffu, m, 1));
    m = fmaxf(m, __shfl_xor_sync(0xffffffffu, m, 2));
    m = fmaxf(m, __shfl_xor_sync(0xffffffffu, m, 4));
    float s = 0.0f;
    #pragma unroll
    for (int i = 0; i < 11; i++) s += __expf(v[i] - m);
    s += __shfl_xor_sync(0xffffffffu, s, 1);
    s += __shfl_xor_sync(0xffffffffu, s, 2);
    s += __shfl_xor_sync(0xffffffffu, s, 4);

    bool is_pos = false;
    float slv = 0.0f, cev = 0.0f;
    if (sub == 0) {
        float lse = m + logf(s);
        int p   = tile * TILE + row;
        int idx = b * P + p;
        float bo = g_btover[idx];
        int   bi = g_btidx[idx];
        // force-match (ascending g == sequential scatter, last wins)
        #pragma unroll
        for (int g = 0; g < G; g++)
            if (sbestp[g] == p) { bo = 2.0f; bi = g; }

        int lab = slab[bi];
        int conf_t = (bo < POS_T) ? ((bo < NEG_T) ? 0 : -1) : lab;
        bool pos = conf_t > 0;
        is_pos = pos;
        // lc for ranking: zero for pos/neutral, lse-conf0 for negatives (>= 0)
        float lc = (pos || conf_t < 0) ? 0.0f : fmaxf(lse - srow[0], 0.0f);
        g_lcbits[idx] = __float_as_uint(lc);
        if (pos) {
            cev = lse - srow[conf_t];   // positive CE
            const float4 pr = *(const float4*)(priors + (size_t)idx * 4);
            const float4 ld = *(const float4*)(loc    + (size_t)idx * 4);
            float gx1 = sgb[bi*4+0], gy1 = sgb[bi*4+1];
            float gx2 = sgb[bi*4+2], gy2 = sgb[bi*4+3];
            float t0 = ((gx1 + gx2) * 0.5f - pr.x) / (VAR0 * pr.z);
            float t1 = ((gy1 + gy2) * 0.5f - pr.y) / (VAR0 * pr.w);
            float t2 = logf(fmaxf((gx2 - gx1) / pr.z, 1e-8f)) / VAR1;
            float t3 = logf(fmaxf((gy2 - gy1) / pr.w, 1e-8f)) / VAR1;
            float d;
            d = ld.x - t0; slv += (fabsf(d) < 1.0f) ? 0.5f * d * d : fabsf(d) - 0.5f;
            d = ld.y - t1; slv += (fabsf(d) < 1.0f) ? 0.5f * d * d : fabsf(d) - 0.5f;
            d = ld.z - t2; slv += (fabsf(d) < 1.0f) ? 0.5f * d * d : fabsf(d) - 0.5f;
            d = ld.w - t3; slv += (fabsf(d) < 1.0f) ? 0.5f * d * d : fabsf(d) - 0.5f;
        }
    }
    // block-reduce numpos, sumSL1, sumPosCE
    unsigned bal = __ballot_sync(0xffffffffu, is_pos);
    #pragma unroll
    for (int o = 16; o > 0; o >>= 1) {
        slv += __shfl_xor_sync(0xffffffffu, slv, o);
        cev += __shfl_xor_sync(0xffffffffu, cev, o);
    }
    int w = t >> 5;
    if ((t & 31) == 0) { s_pos[w] = __popc(bal); s_sB[w] = slv; s_sC[w] = cev; }
    __syncthreads();
    if (t == 0) {
        int c = 0; float tB = 0.0f, tC = 0.0f;
        #pragma unroll
        for (int i = 0; i < CONF_THREADS / 32; i++) { c += s_pos[i]; tB += s_sB[i]; tC += s_sC[i]; }
        if (c)  atomicAdd(&g_numpos[b], c);
        if (tB != 0.0f) atomicAdd(&g_sumB[b], (double)tB);
        if (tC != 0.0f) atomicAdd(&g_sumC[b], (double)tC);
    }
}

// ---- shuffle-based block suffix sum (1024 threads): returns sum_{j>=t} c_j ----
__device__ __forceinline__ int block_suffix_incl(int c, int t, int* wsmem) {
    int lane = t & 31, w = t >> 5;
    int v = c;
    #pragma unroll
    for (int off = 1; off < 32; off <<= 1) {
        int u = __shfl_down_sync(0xffffffffu, v, off);
        if (lane + off < 32) v += u;
    }
    if (lane == 0) wsmem[w] = v;   // warp total
    __syncthreads();
    if (t < 32) {
        int x = wsmem[t];
        #pragma unroll
        for (int off = 1; off < 32; off <<= 1) {
            int u = __shfl_down_sync(0xffffffffu, x, off);
            if (t + off < 32) x += u;
        }
        wsmem[t] = x;              // suffix of warp totals, incl own warp
    }
    __syncthreads();
    int add = (w + 1 < 32) ? wsmem[w + 1] : 0;
    return v + add;
}

// -------- kernel 3: register-cached 3-level threshold + masked sum + output --------
// Each thread caches its 19 lc values in registers (one batched load wave),
// then all histogram levels + the final sum run from registers.
// neg-CE identity: for conf_t==0, ce == lc exactly; ties at T share value T, so
//   negCE = sum_{lc_bits > T} lc  +  (k - cntGT) * float(T)
// Tail padding with value 0 is neutral: appending minima never changes the
// k-th largest, 0 is never > T, and the formula uses only (k, cntGT, T).
__global__ __launch_bounds__(1024)
void k_select(float* __restrict__ out) {
    __shared__ unsigned hist[2048];   // 8KB, reused across levels
    __shared__ int wsmem[32];
    __shared__ int s_bin, s_r;
    __shared__ double sS[32];
    __shared__ int sN[32];

    int b = blockIdx.x, t = threadIdx.x;
    int lane = t & 31;
    const unsigned* lc = g_lcbits + b * P;
    int numpos = g_numpos[b];
    int k = NPR * numpos;
    if (k > P - 1) k = P - 1;

    constexpr int NITER = (P + 1023) / 1024;   // 19
    unsigned vals[NITER];
    #pragma unroll
    for (int i = 0; i < NITER; i++) {
        int p = t + i * 1024;
        vals[i] = (p < P) ? lc[p] : 0u;        // batched independent LDGs (MLP=19)
    }

    // ---- level 1: 2048 bins on bits>>20 (warp-aggregated smem atomics) ----
    hist[t] = 0u; hist[t + 1024] = 0u;
    __syncthreads();
    #pragma unroll
    for (int i = 0; i < NITER; i++) {
        unsigned bin = vals[i] >> 20;          // < 2048 (lc >= 0 clamped)
        unsigned same = __match_any_sync(0xffffffffu, bin);
        if ((__ffs(same) - 1) == lane) atomicAdd(&hist[bin], (unsigned)__popc(same));
    }
    __syncthreads();
    {
        int c0 = (int)hist[2 * t], c1 = (int)hist[2 * t + 1];
        int S = block_suffix_incl(c0 + c1, t, wsmem);
        int above = S - c0 - c1;
        if (above < k && k <= above + c1) { s_bin = 2 * t + 1; s_r = k - above; }
        else if (above + c1 < k && k <= above + c1 + c0) { s_bin = 2 * t; s_r = k - above - c1; }
    }
    __syncthreads();
    unsigned hb1 = (unsigned)s_bin;
    int r = s_r;
    __syncthreads();

    // ---- level 2: 1024 bins on (bits>>10)&0x3FF, predicated on level-1 bin ----
    hist[t] = 0u;
    __syncthreads();
    #pragma unroll
    for (int i = 0; i < NITER; i++) {
        unsigned v = vals[i];
        bool in = ((v >> 20) == hb1);
        unsigned key = in ? ((v >> 10) & 0x3FFu) : 0xFFFFFFFFu;  // non-members: own group
        unsigned same = __match_any_sync(0xffffffffu, key);
        if (in && (__ffs(same) - 1) == lane) atomicAdd(&hist[key], (unsigned)__popc(same));
    }
    __syncthreads();
    {
        int c = (int)hist[t];
        int S = block_suffix_incl(c, t, wsmem);
        int above = S - c;
        if (above < r && r <= above + c) { s_bin = t; s_r = r - above; }
    }
    __syncthreads();
    unsigned pref = (hb1 << 10) | (unsigned)s_bin;
    r = s_r;
    __syncthreads();

    // ---- level 3: 1024 bins on bits&0x3FF, predicated on top 22 bits ----
    hist[t] = 0u;
    __syncthreads();
    #pragma unroll
    for (int i = 0; i < NITER; i++) {
        unsigned v = vals[i];
        bool in = ((v >> 10) == pref);
        unsigned key = in ? (v & 0x3FFu) : 0xFFFFFFFFu;
        unsigned same = __match_any_sync(0xffffffffu, key);
        if (in && (__ffs(same) - 1) == lane) atomicAdd(&hist[key], (unsigned)__popc(same));
    }
    __syncthreads();
    {
        int c = (int)hist[t];
        int S = block_suffix_incl(c, t, wsmem);
        int above = S - c;
        if (above < r && r <= above + c) { s_bin = t; }
    }
    __syncthreads();
    unsigned T = (pref << 10) | (unsigned)s_bin;   // exact k-th largest lc bits

    // ---- masked sum from registers: S_GT = sum lc where bits > T; cntGT ----
    double S = 0.0; int cnt = 0;
    #pragma unroll
    for (int i = 0; i < NITER; i++) {
        unsigned bits = vals[i];
        if (bits > T) { S += (double)__uint_as_float(bits); cnt++; }
    }
    #pragma unroll
    for (int o = 16; o > 0; o >>= 1) {
        S   += __shfl_xor_sync(0xffffffffu, S, o);
        cnt += __shfl_xor_sync(0xffffffffu, cnt, o);
    }
    int w = t >> 5;
    if (lane == 0) { sS[w] = S; sN[w] = cnt; }
    __syncthreads();
    if (t == 0) {
        double tS = 0.0; int tN = 0;
        #pragma unroll
        for (int i = 0; i < 32; i++) { tS += sS[i]; tN += sN[i]; }
        double negCE = tS + (double)(k - tN) * (double)__uint_as_float(T);
        double lossC = g_sumC[b] + negCE;
        double lossB = g_sumB[b] / (double)max(numpos, 1);
        atomicAdd(&g_acc[0], lossB);
        atomicAdd(&g_acc[1], lossC);
        __threadfence();
        unsigned old = atomicAdd(&g_done, 1u);
        if (old == B - 1) {
            out[0] = (float)(g_acc[0] * (double)BBOX_ALPHA / (double)B);
            out[1] = (float)(g_acc[1] * (double)CONF_ALPHA / (double)B);
        }
    }
}

extern "C" void kernel_launch(void* const* d_in, const int* in_sizes, int n_in,
                              void* d_out, int out_size) {
    const float* loc    = (const float*)d_in[0];
    const float* conf   = (const float*)d_in[1];
    const float* priors = (const float*)d_in[2];
    const float* gtb    = (const float*)d_in[3];
    const int*   gtl    = (const int*)d_in[4];
    float* out = (float*)d_out;

    k_reset<<<1, 256>>>();
    {
        dim3 grid((P + 255) / 256, B);
        k_match<<<grid, 256>>>((const float4*)priors, gtb);
    }
    {
        dim3 grid(P / TILE, B);   // 401 x 16
        k_conf<<<grid, CONF_THREADS>>>(conf, loc, priors, gtb, gtl);
    }
    k_select<<<B, 1024>>>(out);
}